// round 14
// baseline (speedup 1.0000x reference)
#include <cuda_runtime.h>
#include <cuda_fp16.h>
#include <cstdint>

// ---- problem constants (fixed by setup_inputs) ----
#define N_B   2
#define L_DIM 4800
#define S_DIM 4800
#define C_DIM 256
#define L_PAD 4864            // 38 * 128
#define H0 60
#define W0 80
#define H1 60
#define W1 80
#define BRD 2
#define THR_V 0.2f
#define SIM_SCALE 0.0390625f  // 1/25.6 exact

#define NTILES 38             // L_PAD / 128

// ---- scratch (device globals; no allocations allowed) ----
__device__ __align__(16) float g_rowsum[N_B * L_DIM];
__device__ __align__(16) float g_colsum[N_B * S_DIM];
__device__ __align__(16) float g_colmax[N_B * S_DIM];
__device__ __align__(16) unsigned long long g_rowpack[N_B * L_DIM];

// fp16 operands, rows padded to L_PAD with zeros (statics zero-initialized;
// pad region never written, stays zero)
__device__ __align__(16) __half g_Ah[N_B * L_PAD * C_DIM];
__device__ __align__(16) __half g_Bh[N_B * L_PAD * C_DIM];

// ===========================================================================
// helpers
// ===========================================================================
__device__ __forceinline__ uint32_t smem_u32(const void* p) {
    uint32_t a;
    asm("{ .reg .u64 t; cvta.to.shared.u64 t, %1; cvt.u32.u64 %0, t; }"
        : "=r"(a) : "l"(p));
    return a;
}
__device__ __forceinline__ void cp_async16(uint32_t dst, const void* src) {
    asm volatile("cp.async.cg.shared.global [%0], [%1], 16;"
                 :: "r"(dst), "l"(src));
}
#define CP_COMMIT() asm volatile("cp.async.commit_group;")
#define CP_WAIT(n)  asm volatile("cp.async.wait_group %0;" :: "n"(n))

__device__ __forceinline__ void ldsm4(uint32_t* r, uint32_t addr) {
    asm volatile("ldmatrix.sync.aligned.m8n8.x4.shared.b16 {%0,%1,%2,%3}, [%4];"
                 : "=r"(r[0]), "=r"(r[1]), "=r"(r[2]), "=r"(r[3]) : "r"(addr));
}
__device__ __forceinline__ void mma16816(float* d, const uint32_t* a,
                                         uint32_t b0, uint32_t b1) {
    asm volatile(
        "mma.sync.aligned.m16n8k16.row.col.f32.f16.f16.f32 "
        "{%0,%1,%2,%3}, {%4,%5,%6,%7}, {%8,%9}, {%0,%1,%2,%3};"
        : "+f"(d[0]), "+f"(d[1]), "+f"(d[2]), "+f"(d[3])
        : "r"(a[0]), "r"(a[1]), "r"(a[2]), "r"(a[3]), "r"(b0), "r"(b1));
}

// ===========================================================================
// 1) per-batch fp32 -> fp16 convert (+ fused accumulator zeroing)
// ===========================================================================
__global__ void convert_kernel(const float* __restrict__ A,
                               const float* __restrict__ B, int n) {
    const int i = blockIdx.x * 256 + threadIdx.x;   // quad index within batch
    if (i < L_DIM) {
        g_rowsum[n * L_DIM + i] = 0.0f; g_colsum[n * S_DIM + i] = 0.0f;
        g_colmax[n * S_DIM + i] = 0.0f; g_rowpack[n * L_DIM + i] = 0ull;
    }
    if (i >= L_DIM * C_DIM / 4) return;
    const int row = i >> 6;            // 64 quads per 256-elem row
    const int q   = i & 63;
    const size_t src = (size_t)n * L_DIM * C_DIM + (size_t)i * 4;
    const size_t dst = ((size_t)n * L_PAD + row) * C_DIM + q * 4;

    float4 a = *(const float4*)(A + src);
    __half2 a01 = __floats2half2_rn(a.x, a.y);
    __half2 a23 = __floats2half2_rn(a.z, a.w);
    *(uint2*)(g_Ah + dst) = make_uint2(*(uint32_t*)&a01, *(uint32_t*)&a23);

    float4 b = *(const float4*)(B + src);
    __half2 b01 = __floats2half2_rn(b.x, b.y);
    __half2 b23 = __floats2half2_rn(b.z, b.w);
    *(uint2*)(g_Bh + dst) = make_uint2(*(uint32_t*)&b01, *(uint32_t*)&b23);
}

// ===========================================================================
// 2) mma.sync fp16 GEMM, fp32 accum. 128x128 tile / CTA, 4 warps (2x2),
//    warp tile 64x64, BK=32, 3-stage cp.async, 2 CTAs/SM. Fused epilogue:
//    E = __expf(d*SIM_SCALE) (plain fp32 stores), row/col sums.
//    [UNCHANGED — HMMA issue-pinned]
// ===========================================================================
#define TILE_B   10240          // 128 rows * 80B
#define STAGE_B  (2 * TILE_B)   // A, B
#define NSTAGE   3
#define GEMM_SMEM (NSTAGE * STAGE_B)   // 61440

__global__ __launch_bounds__(128, 2)
void gemm_mma_kernel(float* __restrict__ E, int n) {
    extern __shared__ char smem[];
    __shared__ float sRow[128];
    __shared__ float sCol[128];

    const int tid  = threadIdx.x;
    const int lane = tid & 31;
    const int wid  = tid >> 5;
    const int warp_m = wid >> 1;       // 0..1  (64 rows each)
    const int warp_n = wid & 1;        // 0..1  (64 cols each)
    const int brow = blockIdx.y * 128;
    const int bcol = blockIdx.x * 128;
    const uint32_t sb = smem_u32(smem);

    sRow[tid] = 0.f; sCol[tid] = 0.f;

    const char* srcA = (const char*)(g_Ah + ((size_t)n * L_PAD + brow) * C_DIM);
    const char* srcB = (const char*)(g_Bh + ((size_t)n * L_PAD + bcol) * C_DIM);

    float acc[4][8][4];
    #pragma unroll
    for (int a = 0; a < 4; a++)
        #pragma unroll
        for (int b = 0; b < 8; b++)
            #pragma unroll
            for (int c = 0; c < 4; c++) acc[a][b][c] = 0.f;

    auto prefetch = [&](int c) {
        const uint32_t st = sb + (c % NSTAGE) * STAGE_B;
        const int k0b = c * 64;                    // 32 fp16 = 64 bytes
        #pragma unroll
        for (int u = 0; u < 8; u++) {
            int i = tid + u * 128;
            int t = i >> 9, idx = i & 511, r = idx >> 2, cc = idx & 3;
            const char* src = t ? srcB : srcA;
            cp_async16(st + t * TILE_B + r * 80 + cc * 16,
                       src + (size_t)r * 512 + k0b + cc * 16);
        }
    };

    prefetch(0); CP_COMMIT();
    prefetch(1); CP_COMMIT();

    #pragma unroll 1
    for (int c = 0; c < 8; c++) {
        if (c < 7) CP_WAIT(1); else CP_WAIT(0);
        __syncthreads();
        if (c < 6) { prefetch(c + 2); CP_COMMIT(); }

        const uint32_t st = sb + (c % NSTAGE) * STAGE_B;
        #pragma unroll
        for (int ks = 0; ks < 2; ks++) {
            uint32_t aoff = (uint32_t)((warp_m * 64 + (lane & 15)) * 80
                                       + ks * 32 + (lane >> 4) * 16);
            uint32_t af[4][4];
            #pragma unroll
            for (int tm = 0; tm < 4; tm++)
                ldsm4(af[tm], st + aoff + tm * (16 * 80));
            uint32_t boff = (uint32_t)((warp_n * 64 + (lane & 7) + ((lane >> 4) << 3)) * 80
                                       + ks * 32 + (((lane >> 3) & 1) << 4));
            uint32_t bf[4][4];
            #pragma unroll
            for (int p = 0; p < 4; p++)
                ldsm4(bf[p], st + TILE_B + boff + p * (16 * 80));
            #pragma unroll
            for (int tm = 0; tm < 4; tm++) {
                #pragma unroll
                for (int tn = 0; tn < 8; tn++) {
                    const int p = tn >> 1, h = (tn & 1) * 2;
                    mma16816(acc[tm][tn], af[tm], bf[p][h], bf[p][h + 1]);
                }
            }
        }
    }

    // ---- epilogue ----
    float cp[8][2];
    #pragma unroll
    for (int tn = 0; tn < 8; tn++) { cp[tn][0] = 0.f; cp[tn][1] = 0.f; }

    float* Eb = E + (size_t)n * L_DIM * S_DIM;
    #pragma unroll
    for (int tm = 0; tm < 4; tm++) {
        const int lr0 = warp_m * 64 + tm * 16 + (lane >> 2);
        const int gr0 = brow + lr0, gr1 = gr0 + 8;
        const bool ok0 = gr0 < L_DIM, ok1 = gr1 < L_DIM;
        float rs0 = 0.f, rs1 = 0.f;
        float* p0 = Eb + (size_t)gr0 * S_DIM;
        float* p1 = Eb + (size_t)gr1 * S_DIM;
        #pragma unroll
        for (int tn = 0; tn < 8; tn++) {
            const int gc = bcol + warp_n * 64 + tn * 8 + (lane & 3) * 2;
            const bool okc = gc < S_DIM;
            float e0 = __expf(acc[tm][tn][0] * SIM_SCALE);
            float e1 = __expf(acc[tm][tn][1] * SIM_SCALE);
            float e2 = __expf(acc[tm][tn][2] * SIM_SCALE);
            float e3 = __expf(acc[tm][tn][3] * SIM_SCALE);
            if (ok0 && okc) *(float2*)(p0 + gc) = make_float2(e0, e1);
            if (ok1 && okc) *(float2*)(p1 + gc) = make_float2(e2, e3);
            float m00 = (ok0 && okc) ? e0 : 0.f;
            float m01 = (ok0 && okc) ? e1 : 0.f;
            float m10 = (ok1 && okc) ? e2 : 0.f;
            float m11 = (ok1 && okc) ? e3 : 0.f;
            rs0 += m00 + m01; rs1 += m10 + m11;
            cp[tn][0] += m00 + m10; cp[tn][1] += m01 + m11;
        }
        rs0 += __shfl_xor_sync(0xffffffffu, rs0, 1);
        rs0 += __shfl_xor_sync(0xffffffffu, rs0, 2);
        rs1 += __shfl_xor_sync(0xffffffffu, rs1, 1);
        rs1 += __shfl_xor_sync(0xffffffffu, rs1, 2);
        if ((lane & 3) == 0) {
            atomicAdd(&sRow[lr0], rs0);
            atomicAdd(&sRow[lr0 + 8], rs1);
        }
    }
    #pragma unroll
    for (int tn = 0; tn < 8; tn++) {
        float cx = cp[tn][0], cy = cp[tn][1];
        cx += __shfl_xor_sync(0xffffffffu, cx, 4);
        cx += __shfl_xor_sync(0xffffffffu, cx, 8);
        cx += __shfl_xor_sync(0xffffffffu, cx, 16);
        cy += __shfl_xor_sync(0xffffffffu, cy, 4);
        cy += __shfl_xor_sync(0xffffffffu, cy, 8);
        cy += __shfl_xor_sync(0xffffffffu, cy, 16);
        if (lane < 4) {
            const int lc = warp_n * 64 + tn * 8 + lane * 2;
            atomicAdd(&sCol[lc], cx);
            atomicAdd(&sCol[lc + 1], cy);
        }
    }
    __syncthreads();
    {
        const int gr = brow + tid;
        if (gr < L_DIM) atomicAdd(&g_rowsum[n * L_DIM + gr], sRow[tid]);
        const int gc = bcol + tid;
        if (gc < S_DIM) atomicAdd(&g_colsum[n * S_DIM + gc], sCol[tid]);
    }
}

// ===========================================================================
// 3) norm pass, thread-owns-row: block = 32-col strip x 256 rows. Each
//    thread normalizes one full row segment (8 float4, contiguous 128B),
//    finds its row max/argmax locally (NO shuffles), one u64 atomicMax.
//    Col max via end-of-block REDUX (nonneg float == uint order) + smem.
// ===========================================================================
#define NORM_ROWS 256
#define NORM_YCHUNKS ((L_DIM + NORM_ROWS - 1) / NORM_ROWS)   // 19
__global__ __launch_bounds__(256)
void norm_pass_kernel(float* __restrict__ conf, int n) {
    __shared__ float s_invcol[32];
    __shared__ unsigned s_cmax[8 * 32];

    const int t    = threadIdx.x;
    const int lane = t & 31;
    const int wid  = t >> 5;
    const int c0   = blockIdx.x * 32;              // col strip base
    const int row  = blockIdx.y * NORM_ROWS + t;   // this thread's row
    const bool active = row < L_DIM;

    if (t < 32) s_invcol[t] = 1.0f / g_colsum[n * S_DIM + c0 + t];
    __syncthreads();

    float4 v[8];
    if (active) {
        const float ir = 1.0f / g_rowsum[n * L_DIM + row];
        float4* rp = (float4*)(conf + (size_t)n * L_DIM * S_DIM
                               + (size_t)row * S_DIM + c0);
        float4 e[8];
        #pragma unroll
        for (int k = 0; k < 8; k++) e[k] = rp[k];      // 8 loads in flight
        #pragma unroll
        for (int k = 0; k < 8; k++) {
            const float4 ic = ((const float4*)s_invcol)[k];
            v[k].x = (e[k].x * ir) * (e[k].x * ic.x);
            v[k].y = (e[k].y * ir) * (e[k].y * ic.y);
            v[k].z = (e[k].z * ir) * (e[k].z * ic.z);
            v[k].w = (e[k].w * ir) * (e[k].w * ic.w);
            rp[k] = v[k];
        }
        // thread-local row max/argmax (ascending cols, strict > = first max)
        float bv = v[0].x; int bi = c0;
        #pragma unroll
        for (int k = 0; k < 8; k++) {
            if (v[k].x > bv) { bv = v[k].x; bi = c0 + 4 * k; }
            if (v[k].y > bv) { bv = v[k].y; bi = c0 + 4 * k + 1; }
            if (v[k].z > bv) { bv = v[k].z; bi = c0 + 4 * k + 2; }
            if (v[k].w > bv) { bv = v[k].w; bi = c0 + 4 * k + 3; }
        }
        unsigned long long p =
            ((unsigned long long)__float_as_uint(bv) << 32) | (unsigned)(~bi);
        atomicMax(&g_rowpack[n * L_DIM + row], p);
    } else {
        #pragma unroll
        for (int k = 0; k < 8; k++) v[k] = make_float4(0.f, 0.f, 0.f, 0.f);
    }

    // per-warp col max via REDUX (values >= 0: uint order == float order)
    #pragma unroll
    for (int k = 0; k < 8; k++) {
        unsigned mx_x = __reduce_max_sync(0xffffffffu, __float_as_uint(v[k].x));
        unsigned mx_y = __reduce_max_sync(0xffffffffu, __float_as_uint(v[k].y));
        unsigned mx_z = __reduce_max_sync(0xffffffffu, __float_as_uint(v[k].z));
        unsigned mx_w = __reduce_max_sync(0xffffffffu, __float_as_uint(v[k].w));
        if (lane == 0) {
            s_cmax[wid * 32 + 4 * k]     = mx_x;
            s_cmax[wid * 32 + 4 * k + 1] = mx_y;
            s_cmax[wid * 32 + 4 * k + 2] = mx_z;
            s_cmax[wid * 32 + 4 * k + 3] = mx_w;
        }
    }
    __syncthreads();
    if (t < 32) {
        unsigned m = s_cmax[t];
        #pragma unroll
        for (int w = 1; w < 8; w++) m = max(m, s_cmax[w * 32 + t]);
        atomicMax((int*)&g_colmax[n * S_DIM + c0 + t], (int)m);
    }
}

// ===========================================================================
// 4) per-batch match extraction (O(1) per row)
// ===========================================================================
__global__ void match_kernel(float* __restrict__ out, int n) {
    const int l = blockIdx.x * 256 + threadIdx.x;
    if (l >= L_DIM) return;
    const int i = n * L_DIM + l;

    const unsigned long long p = g_rowpack[i];
    const float v = __uint_as_float((unsigned)(p >> 32));
    const int   j = (int)(~(unsigned)(p & 0xffffffffu));

    const int y0 = l / W0, x0 = l % W0;
    const int y1 = j / W1, x1 = j % W1;
    const bool b0 = (y0 >= BRD) && (y0 < H0 - BRD) && (x0 >= BRD) && (x0 < W0 - BRD);
    const bool b1 = (y1 >= BRD) && (y1 < H1 - BRD) && (x1 >= BRD) && (x1 < W1 - BRD);
    const bool mv = (v > THR_V) && b0 && b1 && (v == g_colmax[n * S_DIM + j]);

    const int jid = mv ? j : 0;

    const size_t base = (size_t)N_B * L_DIM * S_DIM;
    const int NL = N_B * L_DIM;
    out[base + i]                  = mv ? 1.0f : 0.0f;   // mask_v
    out[base + NL + i]             = (float)jid;         // j_ids
    out[base + 2 * NL + 2 * i]     = (float)(jid % W1);  // mkpts1_c x
    out[base + 2 * NL + 2 * i + 1] = (float)(jid / W1);  // mkpts1_c y
    out[base + 4 * NL + i]         = mv ? v : 0.0f;      // mconf
}

// ===========================================================================
// launch: two-stream per-batch pipeline with PROPER capture fork:
//   legacy: evF -> conv0 -> G0 (ev0) -> N0 -> M0 ......... wait(ev1)
//   s2:     wait(evF) -> conv1 -> wait(ev0) -> G1 -> N1 -> M1 (ev1)
// s2 is forked from the capture stream BEFORE any work lands on it, so all
// s2 nodes are inside the captured graph (the R13 bug).
// ===========================================================================
extern "C" void kernel_launch(void* const* d_in, const int* in_sizes, int n_in,
                              void* d_out, int out_size) {
    const float* feat0 = (const float*)d_in[0];
    const float* feat1 = (const float*)d_in[1];
    float* out = (float*)d_out;

    static cudaStream_t s2 = nullptr;
    static cudaEvent_t evF = nullptr, ev0 = nullptr, ev1 = nullptr;
    if (s2 == nullptr) {
        cudaFuncSetAttribute(gemm_mma_kernel,
                             cudaFuncAttributeMaxDynamicSharedMemorySize, GEMM_SMEM);
        cudaStreamCreateWithFlags(&s2, cudaStreamNonBlocking);
        cudaEventCreateWithFlags(&evF, cudaEventDisableTiming);
        cudaEventCreateWithFlags(&ev0, cudaEventDisableTiming);
        cudaEventCreateWithFlags(&ev1, cudaEventDisableTiming);
    }

    const int convBlocks = (L_DIM * C_DIM / 4 + 255) / 256;   // 1200
    dim3 gGrid(NTILES, NTILES);
    dim3 nGrid(150, NORM_YCHUNKS);
    const int mBlocks = (L_DIM + 255) / 256;                  // 19

    // fork s2 into the capture BEFORE any s2 work
    cudaEventRecord(evF, 0);
    cudaStreamWaitEvent(s2, evF, 0);

    // batch 0 on legacy, batch 1 on s2 (converts run concurrently)
    convert_kernel<<<convBlocks, 256>>>(feat0, feat1, 0);
    convert_kernel<<<convBlocks, 256, 0, s2>>>(feat0, feat1, 1);

    gemm_mma_kernel<<<gGrid, 128, GEMM_SMEM>>>(out, 0);
    cudaEventRecord(ev0, 0);

    cudaStreamWaitEvent(s2, ev0, 0);
    gemm_mma_kernel<<<gGrid, 128, GEMM_SMEM, s2>>>(out, 1);

    norm_pass_kernel<<<nGrid, 256>>>(out, 0);        // legacy, ∥ G1
    match_kernel<<<mBlocks, 256>>>(out, 0);

    norm_pass_kernel<<<nGrid, 256, 0, s2>>>(out, 1);
    match_kernel<<<mBlocks, 256, 0, s2>>>(out, 1);
    cudaEventRecord(ev1, s2);

    cudaStreamWaitEvent(0, ev1, 0);
}

// round 15
// speedup vs baseline: 1.2222x; 1.2222x over previous
#include <cuda_runtime.h>
#include <cuda_fp16.h>
#include <cstdint>

// ---- problem constants (fixed by setup_inputs) ----
#define N_B   2
#define L_DIM 4800
#define S_DIM 4800
#define C_DIM 256
#define L_PAD 4864            // 38 * 128
#define H0 60
#define W0 80
#define H1 60
#define W1 80
#define BRD 2
#define THR_V 0.2f
#define SIM_SCALE 0.0390625f  // 1/25.6 exact

#define NTILES 38             // L_PAD / 128

// ---- scratch (device globals; no allocations allowed) ----
__device__ __align__(16) float g_rowsum[N_B * L_DIM];
__device__ __align__(16) float g_colsum[N_B * S_DIM];
__device__ __align__(16) float g_colmax[N_B * S_DIM];
__device__ __align__(16) unsigned long long g_rowpack[N_B * L_DIM];

// fp16 operands, rows padded to L_PAD with zeros (statics zero-initialized;
// pad region never written, stays zero)
__device__ __align__(16) __half g_Ah[N_B * L_PAD * C_DIM];
__device__ __align__(16) __half g_Bh[N_B * L_PAD * C_DIM];

// ===========================================================================
// helpers
// ===========================================================================
__device__ __forceinline__ uint32_t smem_u32(const void* p) {
    uint32_t a;
    asm("{ .reg .u64 t; cvta.to.shared.u64 t, %1; cvt.u32.u64 %0, t; }"
        : "=r"(a) : "l"(p));
    return a;
}
__device__ __forceinline__ void cp_async16(uint32_t dst, const void* src) {
    asm volatile("cp.async.cg.shared.global [%0], [%1], 16;"
                 :: "r"(dst), "l"(src));
}
#define CP_COMMIT() asm volatile("cp.async.commit_group;")
#define CP_WAIT(n)  asm volatile("cp.async.wait_group %0;" :: "n"(n))

__device__ __forceinline__ void ldsm4(uint32_t* r, uint32_t addr) {
    asm volatile("ldmatrix.sync.aligned.m8n8.x4.shared.b16 {%0,%1,%2,%3}, [%4];"
                 : "=r"(r[0]), "=r"(r[1]), "=r"(r[2]), "=r"(r[3]) : "r"(addr));
}
__device__ __forceinline__ void mma16816(float* d, const uint32_t* a,
                                         uint32_t b0, uint32_t b1) {
    asm volatile(
        "mma.sync.aligned.m16n8k16.row.col.f32.f16.f16.f32 "
        "{%0,%1,%2,%3}, {%4,%5,%6,%7}, {%8,%9}, {%0,%1,%2,%3};"
        : "+f"(d[0]), "+f"(d[1]), "+f"(d[2]), "+f"(d[3])
        : "r"(a[0]), "r"(a[1]), "r"(a[2]), "r"(a[3]), "r"(b0), "r"(b1));
}

// ===========================================================================
// 1) per-batch fp32 -> fp16 convert (+ fused accumulator zeroing)
// ===========================================================================
__global__ void convert_kernel(const float* __restrict__ A,
                               const float* __restrict__ B, int n) {
    const int i = blockIdx.x * 256 + threadIdx.x;   // quad index within batch
    if (i < L_DIM) {
        g_rowsum[n * L_DIM + i] = 0.0f; g_colsum[n * S_DIM + i] = 0.0f;
        g_colmax[n * S_DIM + i] = 0.0f; g_rowpack[n * L_DIM + i] = 0ull;
    }
    if (i >= L_DIM * C_DIM / 4) return;
    const int row = i >> 6;            // 64 quads per 256-elem row
    const int q   = i & 63;
    const size_t src = (size_t)n * L_DIM * C_DIM + (size_t)i * 4;
    const size_t dst = ((size_t)n * L_PAD + row) * C_DIM + q * 4;

    float4 a = *(const float4*)(A + src);
    __half2 a01 = __floats2half2_rn(a.x, a.y);
    __half2 a23 = __floats2half2_rn(a.z, a.w);
    *(uint2*)(g_Ah + dst) = make_uint2(*(uint32_t*)&a01, *(uint32_t*)&a23);

    float4 b = *(const float4*)(B + src);
    __half2 b01 = __floats2half2_rn(b.x, b.y);
    __half2 b23 = __floats2half2_rn(b.z, b.w);
    *(uint2*)(g_Bh + dst) = make_uint2(*(uint32_t*)&b01, *(uint32_t*)&b23);
}

// ===========================================================================
// 2) mma.sync fp16 GEMM, fp32 accum. 128x128 tile / CTA, 4 warps (2x2),
//    warp tile 64x64, BK=32, 3-stage cp.async, 2 CTAs/SM. Fused epilogue:
//    E = __expf(d*SIM_SCALE) (plain fp32 stores), row/col sums.
//    [UNCHANGED — HMMA issue-pinned]
// ===========================================================================
#define TILE_B   10240          // 128 rows * 80B
#define STAGE_B  (2 * TILE_B)   // A, B
#define NSTAGE   3
#define GEMM_SMEM (NSTAGE * STAGE_B)   // 61440

__global__ __launch_bounds__(128, 2)
void gemm_mma_kernel(float* __restrict__ E, int n) {
    extern __shared__ char smem[];
    __shared__ float sRow[128];
    __shared__ float sCol[128];

    const int tid  = threadIdx.x;
    const int lane = tid & 31;
    const int wid  = tid >> 5;
    const int warp_m = wid >> 1;       // 0..1  (64 rows each)
    const int warp_n = wid & 1;        // 0..1  (64 cols each)
    const int brow = blockIdx.y * 128;
    const int bcol = blockIdx.x * 128;
    const uint32_t sb = smem_u32(smem);

    sRow[tid] = 0.f; sCol[tid] = 0.f;

    const char* srcA = (const char*)(g_Ah + ((size_t)n * L_PAD + brow) * C_DIM);
    const char* srcB = (const char*)(g_Bh + ((size_t)n * L_PAD + bcol) * C_DIM);

    float acc[4][8][4];
    #pragma unroll
    for (int a = 0; a < 4; a++)
        #pragma unroll
        for (int b = 0; b < 8; b++)
            #pragma unroll
            for (int c = 0; c < 4; c++) acc[a][b][c] = 0.f;

    auto prefetch = [&](int c) {
        const uint32_t st = sb + (c % NSTAGE) * STAGE_B;
        const int k0b = c * 64;                    // 32 fp16 = 64 bytes
        #pragma unroll
        for (int u = 0; u < 8; u++) {
            int i = tid + u * 128;
            int t = i >> 9, idx = i & 511, r = idx >> 2, cc = idx & 3;
            const char* src = t ? srcB : srcA;
            cp_async16(st + t * TILE_B + r * 80 + cc * 16,
                       src + (size_t)r * 512 + k0b + cc * 16);
        }
    };

    prefetch(0); CP_COMMIT();
    prefetch(1); CP_COMMIT();

    #pragma unroll 1
    for (int c = 0; c < 8; c++) {
        if (c < 7) CP_WAIT(1); else CP_WAIT(0);
        __syncthreads();
        if (c < 6) { prefetch(c + 2); CP_COMMIT(); }

        const uint32_t st = sb + (c % NSTAGE) * STAGE_B;
        #pragma unroll
        for (int ks = 0; ks < 2; ks++) {
            uint32_t aoff = (uint32_t)((warp_m * 64 + (lane & 15)) * 80
                                       + ks * 32 + (lane >> 4) * 16);
            uint32_t af[4][4];
            #pragma unroll
            for (int tm = 0; tm < 4; tm++)
                ldsm4(af[tm], st + aoff + tm * (16 * 80));
            uint32_t boff = (uint32_t)((warp_n * 64 + (lane & 7) + ((lane >> 4) << 3)) * 80
                                       + ks * 32 + (((lane >> 3) & 1) << 4));
            uint32_t bf[4][4];
            #pragma unroll
            for (int p = 0; p < 4; p++)
                ldsm4(bf[p], st + TILE_B + boff + p * (16 * 80));
            #pragma unroll
            for (int tm = 0; tm < 4; tm++) {
                #pragma unroll
                for (int tn = 0; tn < 8; tn++) {
                    const int p = tn >> 1, h = (tn & 1) * 2;
                    mma16816(acc[tm][tn], af[tm], bf[p][h], bf[p][h + 1]);
                }
            }
        }
    }

    // ---- epilogue ----
    float cp[8][2];
    #pragma unroll
    for (int tn = 0; tn < 8; tn++) { cp[tn][0] = 0.f; cp[tn][1] = 0.f; }

    float* Eb = E + (size_t)n * L_DIM * S_DIM;
    #pragma unroll
    for (int tm = 0; tm < 4; tm++) {
        const int lr0 = warp_m * 64 + tm * 16 + (lane >> 2);
        const int gr0 = brow + lr0, gr1 = gr0 + 8;
        const bool ok0 = gr0 < L_DIM, ok1 = gr1 < L_DIM;
        float rs0 = 0.f, rs1 = 0.f;
        float* p0 = Eb + (size_t)gr0 * S_DIM;
        float* p1 = Eb + (size_t)gr1 * S_DIM;
        #pragma unroll
        for (int tn = 0; tn < 8; tn++) {
            const int gc = bcol + warp_n * 64 + tn * 8 + (lane & 3) * 2;
            const bool okc = gc < S_DIM;
            float e0 = __expf(acc[tm][tn][0] * SIM_SCALE);
            float e1 = __expf(acc[tm][tn][1] * SIM_SCALE);
            float e2 = __expf(acc[tm][tn][2] * SIM_SCALE);
            float e3 = __expf(acc[tm][tn][3] * SIM_SCALE);
            if (ok0 && okc) *(float2*)(p0 + gc) = make_float2(e0, e1);
            if (ok1 && okc) *(float2*)(p1 + gc) = make_float2(e2, e3);
            float m00 = (ok0 && okc) ? e0 : 0.f;
            float m01 = (ok0 && okc) ? e1 : 0.f;
            float m10 = (ok1 && okc) ? e2 : 0.f;
            float m11 = (ok1 && okc) ? e3 : 0.f;
            rs0 += m00 + m01; rs1 += m10 + m11;
            cp[tn][0] += m00 + m10; cp[tn][1] += m01 + m11;
        }
        rs0 += __shfl_xor_sync(0xffffffffu, rs0, 1);
        rs0 += __shfl_xor_sync(0xffffffffu, rs0, 2);
        rs1 += __shfl_xor_sync(0xffffffffu, rs1, 1);
        rs1 += __shfl_xor_sync(0xffffffffu, rs1, 2);
        if ((lane & 3) == 0) {
            atomicAdd(&sRow[lr0], rs0);
            atomicAdd(&sRow[lr0 + 8], rs1);
        }
    }
    #pragma unroll
    for (int tn = 0; tn < 8; tn++) {
        float cx = cp[tn][0], cy = cp[tn][1];
        cx += __shfl_xor_sync(0xffffffffu, cx, 4);
        cx += __shfl_xor_sync(0xffffffffu, cx, 8);
        cx += __shfl_xor_sync(0xffffffffu, cx, 16);
        cy += __shfl_xor_sync(0xffffffffu, cy, 4);
        cy += __shfl_xor_sync(0xffffffffu, cy, 8);
        cy += __shfl_xor_sync(0xffffffffu, cy, 16);
        if (lane < 4) {
            const int lc = warp_n * 64 + tn * 8 + lane * 2;
            atomicAdd(&sCol[lc], cx);
            atomicAdd(&sCol[lc + 1], cy);
        }
    }
    __syncthreads();
    {
        const int gr = brow + tid;
        if (gr < L_DIM) atomicAdd(&g_rowsum[n * L_DIM + gr], sRow[tid]);
        const int gc = bcol + tid;
        if (gc < S_DIM) atomicAdd(&g_colsum[n * S_DIM + gc], sCol[tid]);
    }
}

// ===========================================================================
// 3) fused norm pass (R12 body — proven): reciprocals in-block,
//    conf = (E*invr)*(E*invc) in place (plain ld/st); per-row packed
//    max/argmax (u64 atomicMax); per-col max (int atomicMax).
// ===========================================================================
#define ROW_CHUNK 960
#define N_ROW_CHUNKS 5
__global__ __launch_bounds__(256)
void norm_pass_kernel(float* __restrict__ conf, int n) {
    __shared__ float s_invrow[ROW_CHUNK];
    __shared__ float s_invcol[32];

    const int rbase = blockIdx.y * ROW_CHUNK;
    const int t     = threadIdx.x;
    for (int i = t; i < ROW_CHUNK; i += 256)
        s_invrow[i] = 1.0f / g_rowsum[n * L_DIM + rbase + i];
    if (t < 32)
        s_invcol[t] = 1.0f / g_colsum[n * S_DIM + blockIdx.x * 32 + t];
    __syncthreads();

    const int c4 = blockIdx.x * 8 + (t & 7);     // float4 col index < 1200
    const int r0 = t >> 3;                        // 0..31
    float4* base = (float4*)(conf + (size_t)n * L_DIM * S_DIM) + c4;
    const float4 ic = ((const float4*)s_invcol)[t & 7];
    unsigned long long* rowpack = g_rowpack + n * L_DIM;
    const int colbase = c4 * 4;

    float4 cm = make_float4(0.f, 0.f, 0.f, 0.f);
    #pragma unroll 2
    for (int it = 0; it < ROW_CHUNK / 32; it++) {
        const int lrow = r0 + it * 32;
        const int row  = rbase + lrow;
        const float ir = s_invrow[lrow];
        float4 e = base[(size_t)row * 1200];
        float4 v;
        v.x = (e.x * ir) * (e.x * ic.x);
        v.y = (e.y * ir) * (e.y * ic.y);
        v.z = (e.z * ir) * (e.z * ic.z);
        v.w = (e.w * ir) * (e.w * ic.w);
        base[(size_t)row * 1200] = v;
        cm.x = fmaxf(cm.x, v.x); cm.y = fmaxf(cm.y, v.y);
        cm.z = fmaxf(cm.z, v.z); cm.w = fmaxf(cm.w, v.w);

        float bv = v.x; int bi = colbase;
        if (v.y > bv) { bv = v.y; bi = colbase + 1; }
        if (v.z > bv) { bv = v.z; bi = colbase + 2; }
        if (v.w > bv) { bv = v.w; bi = colbase + 3; }
        unsigned long long p =
            ((unsigned long long)__float_as_uint(bv) << 32) | (unsigned)(~bi);
        unsigned long long q;
        q = __shfl_xor_sync(0xffffffffu, p, 1); p = p > q ? p : q;
        q = __shfl_xor_sync(0xffffffffu, p, 2); p = p > q ? p : q;
        q = __shfl_xor_sync(0xffffffffu, p, 4); p = p > q ? p : q;
        if ((t & 7) == 0) atomicMax(&rowpack[row], p);
    }
    int* cmp = (int*)(g_colmax + n * S_DIM + colbase);
    atomicMax(cmp + 0, __float_as_int(cm.x));
    atomicMax(cmp + 1, __float_as_int(cm.y));
    atomicMax(cmp + 2, __float_as_int(cm.z));
    atomicMax(cmp + 3, __float_as_int(cm.w));
}

// ===========================================================================
// 4) per-batch match extraction (O(1) per row)
// ===========================================================================
__global__ void match_kernel(float* __restrict__ out, int n) {
    const int l = blockIdx.x * 256 + threadIdx.x;
    if (l >= L_DIM) return;
    const int i = n * L_DIM + l;

    const unsigned long long p = g_rowpack[i];
    const float v = __uint_as_float((unsigned)(p >> 32));
    const int   j = (int)(~(unsigned)(p & 0xffffffffu));

    const int y0 = l / W0, x0 = l % W0;
    const int y1 = j / W1, x1 = j % W1;
    const bool b0 = (y0 >= BRD) && (y0 < H0 - BRD) && (x0 >= BRD) && (x0 < W0 - BRD);
    const bool b1 = (y1 >= BRD) && (y1 < H1 - BRD) && (x1 >= BRD) && (x1 < W1 - BRD);
    const bool mv = (v > THR_V) && b0 && b1 && (v == g_colmax[n * S_DIM + j]);

    const int jid = mv ? j : 0;

    const size_t base = (size_t)N_B * L_DIM * S_DIM;
    const int NL = N_B * L_DIM;
    out[base + i]                  = mv ? 1.0f : 0.0f;   // mask_v
    out[base + NL + i]             = (float)jid;         // j_ids
    out[base + 2 * NL + 2 * i]     = (float)(jid % W1);  // mkpts1_c x
    out[base + 2 * NL + 2 * i + 1] = (float)(jid / W1);  // mkpts1_c y
    out[base + 4 * NL + i]         = mv ? v : 0.0f;      // mconf
}

// ===========================================================================
// launch: two-stream per-batch pipeline (R12 structure; proper evF fork):
//   legacy: evF -> conv0 -> G0 (ev0) -> N0 -> M0 ......... wait(ev1)
//   s2:     wait(evF) -> conv1 -> wait(ev0) -> G1 -> N1 -> M1 (ev1)
// ===========================================================================
extern "C" void kernel_launch(void* const* d_in, const int* in_sizes, int n_in,
                              void* d_out, int out_size) {
    const float* feat0 = (const float*)d_in[0];
    const float* feat1 = (const float*)d_in[1];
    float* out = (float*)d_out;

    static cudaStream_t s2 = nullptr;
    static cudaEvent_t evF = nullptr, ev0 = nullptr, ev1 = nullptr;
    if (s2 == nullptr) {
        cudaFuncSetAttribute(gemm_mma_kernel,
                             cudaFuncAttributeMaxDynamicSharedMemorySize, GEMM_SMEM);
        cudaStreamCreateWithFlags(&s2, cudaStreamNonBlocking);
        cudaEventCreateWithFlags(&evF, cudaEventDisableTiming);
        cudaEventCreateWithFlags(&ev0, cudaEventDisableTiming);
        cudaEventCreateWithFlags(&ev1, cudaEventDisableTiming);
    }

    const int convBlocks = (L_DIM * C_DIM / 4 + 255) / 256;   // 1200
    dim3 gGrid(NTILES, NTILES);
    dim3 nGrid(150, N_ROW_CHUNKS);
    const int mBlocks = (L_DIM + 255) / 256;                  // 19

    // fork s2 into the capture BEFORE any s2 work (R13 lesson)
    cudaEventRecord(evF, 0);
    cudaStreamWaitEvent(s2, evF, 0);

    convert_kernel<<<convBlocks, 256>>>(feat0, feat1, 0);
    convert_kernel<<<convBlocks, 256, 0, s2>>>(feat0, feat1, 1);

    gemm_mma_kernel<<<gGrid, 128, GEMM_SMEM>>>(out, 0);
    cudaEventRecord(ev0, 0);

    cudaStreamWaitEvent(s2, ev0, 0);
    gemm_mma_kernel<<<gGrid, 128, GEMM_SMEM, s2>>>(out, 1);

    norm_pass_kernel<<<nGrid, 256>>>(out, 0);        // legacy, ∥ G1
    match_kernel<<<mBlocks, 256>>>(out, 0);          // hidden under G1/N1

    norm_pass_kernel<<<nGrid, 256, 0, s2>>>(out, 1);
    match_kernel<<<mBlocks, 256, 0, s2>>>(out, 1);
    cudaEventRecord(ev1, s2);

    cudaStreamWaitEvent(0, ev1, 0);
}

// round 16
// speedup vs baseline: 1.2603x; 1.0312x over previous
#include <cuda_runtime.h>
#include <cuda_fp16.h>
#include <cstdint>

// ---- problem constants (fixed by setup_inputs) ----
#define N_B   2
#define L_DIM 4800
#define S_DIM 4800
#define C_DIM 256
#define L_PAD 4864            // 38 * 128
#define H0 60
#define W0 80
#define H1 60
#define W1 80
#define BRD 2
#define THR_V 0.2f
#define SIM_SCALE 0.0390625f  // 1/25.6 exact

#define NTILES 38             // L_PAD / 128

// ---- scratch (device globals; no allocations allowed) ----
__device__ __align__(16) float g_rowsum[N_B * L_DIM];
__device__ __align__(16) float g_colsum[N_B * S_DIM];
__device__ __align__(16) float g_colmax[N_B * S_DIM];
__device__ __align__(16) unsigned long long g_rowpack[N_B * L_DIM];

// fp16 operands, rows padded to L_PAD with zeros (statics zero-initialized;
// pad region never written, stays zero)
__device__ __align__(16) __half g_Ah[N_B * L_PAD * C_DIM];
__device__ __align__(16) __half g_Bh[N_B * L_PAD * C_DIM];

// ===========================================================================
// helpers
// ===========================================================================
__device__ __forceinline__ uint32_t smem_u32(const void* p) {
    uint32_t a;
    asm("{ .reg .u64 t; cvta.to.shared.u64 t, %1; cvt.u32.u64 %0, t; }"
        : "=r"(a) : "l"(p));
    return a;
}
__device__ __forceinline__ void cp_async16(uint32_t dst, const void* src) {
    asm volatile("cp.async.cg.shared.global [%0], [%1], 16;"
                 :: "r"(dst), "l"(src));
}
#define CP_COMMIT() asm volatile("cp.async.commit_group;")
#define CP_WAIT(n)  asm volatile("cp.async.wait_group %0;" :: "n"(n))

__device__ __forceinline__ void ldsm4(uint32_t* r, uint32_t addr) {
    asm volatile("ldmatrix.sync.aligned.m8n8.x4.shared.b16 {%0,%1,%2,%3}, [%4];"
                 : "=r"(r[0]), "=r"(r[1]), "=r"(r[2]), "=r"(r[3]) : "r"(addr));
}
__device__ __forceinline__ void mma16816(float* d, const uint32_t* a,
                                         uint32_t b0, uint32_t b1) {
    asm volatile(
        "mma.sync.aligned.m16n8k16.row.col.f32.f16.f16.f32 "
        "{%0,%1,%2,%3}, {%4,%5,%6,%7}, {%8,%9}, {%0,%1,%2,%3};"
        : "+f"(d[0]), "+f"(d[1]), "+f"(d[2]), "+f"(d[3])
        : "r"(a[0]), "r"(a[1]), "r"(a[2]), "r"(a[3]), "r"(b0), "r"(b1));
}

// ===========================================================================
// 1) per-batch fp32 -> fp16 convert (+ fused accumulator zeroing)
// ===========================================================================
__global__ void convert_kernel(const float* __restrict__ A,
                               const float* __restrict__ B, int n) {
    const int i = blockIdx.x * 256 + threadIdx.x;   // quad index within batch
    if (i < L_DIM) {
        g_rowsum[n * L_DIM + i] = 0.0f; g_colsum[n * S_DIM + i] = 0.0f;
        g_colmax[n * S_DIM + i] = 0.0f; g_rowpack[n * L_DIM + i] = 0ull;
    }
    if (i >= L_DIM * C_DIM / 4) return;
    const int row = i >> 6;            // 64 quads per 256-elem row
    const int q   = i & 63;
    const size_t src = (size_t)n * L_DIM * C_DIM + (size_t)i * 4;
    const size_t dst = ((size_t)n * L_PAD + row) * C_DIM + q * 4;

    float4 a = *(const float4*)(A + src);
    __half2 a01 = __floats2half2_rn(a.x, a.y);
    __half2 a23 = __floats2half2_rn(a.z, a.w);
    *(uint2*)(g_Ah + dst) = make_uint2(*(uint32_t*)&a01, *(uint32_t*)&a23);

    float4 b = *(const float4*)(B + src);
    __half2 b01 = __floats2half2_rn(b.x, b.y);
    __half2 b23 = __floats2half2_rn(b.z, b.w);
    *(uint2*)(g_Bh + dst) = make_uint2(*(uint32_t*)&b01, *(uint32_t*)&b23);
}

// ===========================================================================
// 2) mma.sync fp16 GEMM, fp32 accum — R6 configuration (fastest measured):
//    128x128 tile / CTA, 8 warps (2x4), warp tile 64x32, BK=32, 3-stage
//    cp.async, 2 CTAs/SM. Fused epilogue: E = __expf(d*SIM_SCALE) (plain
//    fp32 stores), row/col sums. Smem pitch 80B (conflict-free).
// ===========================================================================
#define TILE_B   10240          // 128 rows * 80B
#define STAGE_B  (2 * TILE_B)   // A, B
#define NSTAGE   3
#define GEMM_SMEM (NSTAGE * STAGE_B)   // 61440

__global__ __launch_bounds__(256, 2)
void gemm_mma_kernel(float* __restrict__ E, int n) {
    extern __shared__ char smem[];
    __shared__ float sRow[128];
    __shared__ float sCol[128];

    const int tid  = threadIdx.x;
    const int lane = tid & 31;
    const int wid  = tid >> 5;
    const int warp_m = wid >> 2;       // 0..1  (64 rows each)
    const int warp_n = wid & 3;        // 0..3  (32 cols each)
    const int brow = blockIdx.y * 128;
    const int bcol = blockIdx.x * 128;
    const uint32_t sb = smem_u32(smem);

    if (tid < 128) { sRow[tid] = 0.f; sCol[tid] = 0.f; }

    const char* srcA = (const char*)(g_Ah + ((size_t)n * L_PAD + brow) * C_DIM);
    const char* srcB = (const char*)(g_Bh + ((size_t)n * L_PAD + bcol) * C_DIM);

    float acc[4][4][4];
    #pragma unroll
    for (int a = 0; a < 4; a++)
        #pragma unroll
        for (int b = 0; b < 4; b++)
            #pragma unroll
            for (int c = 0; c < 4; c++) acc[a][b][c] = 0.f;

    // prefetch chunk c into stage c%3: 1024 16B units, 256 threads x 4
    auto prefetch = [&](int c) {
        const uint32_t st = sb + (c % NSTAGE) * STAGE_B;
        const int k0b = c * 64;                    // 32 fp16 = 64 bytes
        #pragma unroll
        for (int u = 0; u < 4; u++) {
            int i = tid + u * 256;
            int t = i >> 9, idx = i & 511, r = idx >> 2, cc = idx & 3;
            const char* src = t ? srcB : srcA;
            cp_async16(st + t * TILE_B + r * 80 + cc * 16,
                       src + (size_t)r * 512 + k0b + cc * 16);
        }
    };

    prefetch(0); CP_COMMIT();
    prefetch(1); CP_COMMIT();

    #pragma unroll 1
    for (int c = 0; c < 8; c++) {
        if (c < 7) CP_WAIT(1); else CP_WAIT(0);
        __syncthreads();
        if (c < 6) { prefetch(c + 2); CP_COMMIT(); }

        const uint32_t st = sb + (c % NSTAGE) * STAGE_B;
        #pragma unroll
        for (int ks = 0; ks < 2; ks++) {
            uint32_t aoff = (uint32_t)((warp_m * 64 + (lane & 15)) * 80
                                       + ks * 32 + (lane >> 4) * 16);
            uint32_t af[4][4];
            #pragma unroll
            for (int tm = 0; tm < 4; tm++)
                ldsm4(af[tm], st + aoff + tm * (16 * 80));
            uint32_t boff = (uint32_t)((warp_n * 32 + (lane & 7) + ((lane >> 4) << 3)) * 80
                                       + ks * 32 + (((lane >> 3) & 1) << 4));
            uint32_t bf[2][4];
            #pragma unroll
            for (int p = 0; p < 2; p++)
                ldsm4(bf[p], st + TILE_B + boff + p * (16 * 80));
            #pragma unroll
            for (int tm = 0; tm < 4; tm++) {
                #pragma unroll
                for (int tn = 0; tn < 4; tn++) {
                    const int p = tn >> 1, h = (tn & 1) * 2;
                    mma16816(acc[tm][tn], af[tm], bf[p][h], bf[p][h + 1]);
                }
            }
        }
    }

    // ---- epilogue ----
    float cp[4][2];
    #pragma unroll
    for (int tn = 0; tn < 4; tn++) { cp[tn][0] = 0.f; cp[tn][1] = 0.f; }

    float* Eb = E + (size_t)n * L_DIM * S_DIM;
    #pragma unroll
    for (int tm = 0; tm < 4; tm++) {
        const int lr0 = warp_m * 64 + tm * 16 + (lane >> 2);
        const int gr0 = brow + lr0, gr1 = gr0 + 8;
        const bool ok0 = gr0 < L_DIM, ok1 = gr1 < L_DIM;
        float rs0 = 0.f, rs1 = 0.f;
        float* p0 = Eb + (size_t)gr0 * S_DIM;
        float* p1 = Eb + (size_t)gr1 * S_DIM;
        #pragma unroll
        for (int tn = 0; tn < 4; tn++) {
            const int gc = bcol + warp_n * 32 + tn * 8 + (lane & 3) * 2;
            const bool okc = gc < S_DIM;
            float e0 = __expf(acc[tm][tn][0] * SIM_SCALE);
            float e1 = __expf(acc[tm][tn][1] * SIM_SCALE);
            float e2 = __expf(acc[tm][tn][2] * SIM_SCALE);
            float e3 = __expf(acc[tm][tn][3] * SIM_SCALE);
            if (ok0 && okc) *(float2*)(p0 + gc) = make_float2(e0, e1);
            if (ok1 && okc) *(float2*)(p1 + gc) = make_float2(e2, e3);
            float m00 = (ok0 && okc) ? e0 : 0.f;
            float m01 = (ok0 && okc) ? e1 : 0.f;
            float m10 = (ok1 && okc) ? e2 : 0.f;
            float m11 = (ok1 && okc) ? e3 : 0.f;
            rs0 += m00 + m01; rs1 += m10 + m11;
            cp[tn][0] += m00 + m10; cp[tn][1] += m01 + m11;
        }
        rs0 += __shfl_xor_sync(0xffffffffu, rs0, 1);
        rs0 += __shfl_xor_sync(0xffffffffu, rs0, 2);
        rs1 += __shfl_xor_sync(0xffffffffu, rs1, 1);
        rs1 += __shfl_xor_sync(0xffffffffu, rs1, 2);
        if ((lane & 3) == 0) {
            atomicAdd(&sRow[lr0], rs0);
            atomicAdd(&sRow[lr0 + 8], rs1);
        }
    }
    #pragma unroll
    for (int tn = 0; tn < 4; tn++) {
        float cx = cp[tn][0], cy = cp[tn][1];
        cx += __shfl_xor_sync(0xffffffffu, cx, 4);
        cx += __shfl_xor_sync(0xffffffffu, cx, 8);
        cx += __shfl_xor_sync(0xffffffffu, cx, 16);
        cy += __shfl_xor_sync(0xffffffffu, cy, 4);
        cy += __shfl_xor_sync(0xffffffffu, cy, 8);
        cy += __shfl_xor_sync(0xffffffffu, cy, 16);
        if (lane < 4) {
            const int lc = warp_n * 32 + tn * 8 + lane * 2;
            atomicAdd(&sCol[lc], cx);
            atomicAdd(&sCol[lc + 1], cy);
        }
    }
    __syncthreads();
    if (tid < 128) {
        const int gr = brow + tid;
        if (gr < L_DIM) atomicAdd(&g_rowsum[n * L_DIM + gr], sRow[tid]);
        const int gc = bcol + tid;
        if (gc < S_DIM) atomicAdd(&g_colsum[n * S_DIM + gc], sCol[tid]);
    }
}

// ===========================================================================
// 3) fused norm pass (R12 body — proven): reciprocals in-block,
//    conf = (E*invr)*(E*invc) in place (plain ld/st); per-row packed
//    max/argmax (u64 atomicMax); per-col max (int atomicMax).
// ===========================================================================
#define ROW_CHUNK 960
#define N_ROW_CHUNKS 5
__global__ __launch_bounds__(256)
void norm_pass_kernel(float* __restrict__ conf, int n) {
    __shared__ float s_invrow[ROW_CHUNK];
    __shared__ float s_invcol[32];

    const int rbase = blockIdx.y * ROW_CHUNK;
    const int t     = threadIdx.x;
    for (int i = t; i < ROW_CHUNK; i += 256)
        s_invrow[i] = 1.0f / g_rowsum[n * L_DIM + rbase + i];
    if (t < 32)
        s_invcol[t] = 1.0f / g_colsum[n * S_DIM + blockIdx.x * 32 + t];
    __syncthreads();

    const int c4 = blockIdx.x * 8 + (t & 7);     // float4 col index < 1200
    const int r0 = t >> 3;                        // 0..31
    float4* base = (float4*)(conf + (size_t)n * L_DIM * S_DIM) + c4;
    const float4 ic = ((const float4*)s_invcol)[t & 7];
    unsigned long long* rowpack = g_rowpack + n * L_DIM;
    const int colbase = c4 * 4;

    float4 cm = make_float4(0.f, 0.f, 0.f, 0.f);
    #pragma unroll 2
    for (int it = 0; it < ROW_CHUNK / 32; it++) {
        const int lrow = r0 + it * 32;
        const int row  = rbase + lrow;
        const float ir = s_invrow[lrow];
        float4 e = base[(size_t)row * 1200];
        float4 v;
        v.x = (e.x * ir) * (e.x * ic.x);
        v.y = (e.y * ir) * (e.y * ic.y);
        v.z = (e.z * ir) * (e.z * ic.z);
        v.w = (e.w * ir) * (e.w * ic.w);
        base[(size_t)row * 1200] = v;
        cm.x = fmaxf(cm.x, v.x); cm.y = fmaxf(cm.y, v.y);
        cm.z = fmaxf(cm.z, v.z); cm.w = fmaxf(cm.w, v.w);

        float bv = v.x; int bi = colbase;
        if (v.y > bv) { bv = v.y; bi = colbase + 1; }
        if (v.z > bv) { bv = v.z; bi = colbase + 2; }
        if (v.w > bv) { bv = v.w; bi = colbase + 3; }
        unsigned long long p =
            ((unsigned long long)__float_as_uint(bv) << 32) | (unsigned)(~bi);
        unsigned long long q;
        q = __shfl_xor_sync(0xffffffffu, p, 1); p = p > q ? p : q;
        q = __shfl_xor_sync(0xffffffffu, p, 2); p = p > q ? p : q;
        q = __shfl_xor_sync(0xffffffffu, p, 4); p = p > q ? p : q;
        if ((t & 7) == 0) atomicMax(&rowpack[row], p);
    }
    int* cmp = (int*)(g_colmax + n * S_DIM + colbase);
    atomicMax(cmp + 0, __float_as_int(cm.x));
    atomicMax(cmp + 1, __float_as_int(cm.y));
    atomicMax(cmp + 2, __float_as_int(cm.z));
    atomicMax(cmp + 3, __float_as_int(cm.w));
}

// ===========================================================================
// 4) per-batch match extraction (O(1) per row)
// ===========================================================================
__global__ void match_kernel(float* __restrict__ out, int n) {
    const int l = blockIdx.x * 256 + threadIdx.x;
    if (l >= L_DIM) return;
    const int i = n * L_DIM + l;

    const unsigned long long p = g_rowpack[i];
    const float v = __uint_as_float((unsigned)(p >> 32));
    const int   j = (int)(~(unsigned)(p & 0xffffffffu));

    const int y0 = l / W0, x0 = l % W0;
    const int y1 = j / W1, x1 = j % W1;
    const bool b0 = (y0 >= BRD) && (y0 < H0 - BRD) && (x0 >= BRD) && (x0 < W0 - BRD);
    const bool b1 = (y1 >= BRD) && (y1 < H1 - BRD) && (x1 >= BRD) && (x1 < W1 - BRD);
    const bool mv = (v > THR_V) && b0 && b1 && (v == g_colmax[n * S_DIM + j]);

    const int jid = mv ? j : 0;

    const size_t base = (size_t)N_B * L_DIM * S_DIM;
    const int NL = N_B * L_DIM;
    out[base + i]                  = mv ? 1.0f : 0.0f;   // mask_v
    out[base + NL + i]             = (float)jid;         // j_ids
    out[base + 2 * NL + 2 * i]     = (float)(jid % W1);  // mkpts1_c x
    out[base + 2 * NL + 2 * i + 1] = (float)(jid / W1);  // mkpts1_c y
    out[base + 4 * NL + i]         = mv ? v : 0.0f;      // mconf
}

// ===========================================================================
// launch: two-stream per-batch pipeline (R15 structure; proper evF fork):
//   legacy: evF -> conv0 -> G0 (ev0) -> N0 -> M0 ......... wait(ev1)
//   s2:     wait(evF) -> conv1 -> wait(ev0) -> G1 -> N1 -> M1 (ev1)
// ===========================================================================
extern "C" void kernel_launch(void* const* d_in, const int* in_sizes, int n_in,
                              void* d_out, int out_size) {
    const float* feat0 = (const float*)d_in[0];
    const float* feat1 = (const float*)d_in[1];
    float* out = (float*)d_out;

    static cudaStream_t s2 = nullptr;
    static cudaEvent_t evF = nullptr, ev0 = nullptr, ev1 = nullptr;
    if (s2 == nullptr) {
        cudaFuncSetAttribute(gemm_mma_kernel,
                             cudaFuncAttributeMaxDynamicSharedMemorySize, GEMM_SMEM);
        cudaStreamCreateWithFlags(&s2, cudaStreamNonBlocking);
        cudaEventCreateWithFlags(&evF, cudaEventDisableTiming);
        cudaEventCreateWithFlags(&ev0, cudaEventDisableTiming);
        cudaEventCreateWithFlags(&ev1, cudaEventDisableTiming);
    }

    const int convBlocks = (L_DIM * C_DIM / 4 + 255) / 256;   // 1200
    dim3 gGrid(NTILES, NTILES);
    dim3 nGrid(150, N_ROW_CHUNKS);
    const int mBlocks = (L_DIM + 255) / 256;                  // 19

    // fork s2 into the capture BEFORE any s2 work (R13 lesson)
    cudaEventRecord(evF, 0);
    cudaStreamWaitEvent(s2, evF, 0);

    convert_kernel<<<convBlocks, 256>>>(feat0, feat1, 0);
    convert_kernel<<<convBlocks, 256, 0, s2>>>(feat0, feat1, 1);

    gemm_mma_kernel<<<gGrid, 256, GEMM_SMEM>>>(out, 0);
    cudaEventRecord(ev0, 0);

    cudaStreamWaitEvent(s2, ev0, 0);
    gemm_mma_kernel<<<gGrid, 256, GEMM_SMEM, s2>>>(out, 1);

    norm_pass_kernel<<<nGrid, 256>>>(out, 0);        // legacy, ∥ G1
    match_kernel<<<mBlocks, 256>>>(out, 0);          // hidden under G1/N1

    norm_pass_kernel<<<nGrid, 256, 0, s2>>>(out, 1);
    match_kernel<<<mBlocks, 256, 0, s2>>>(out, 1);
    cudaEventRecord(ev1, s2);

    cudaStreamWaitEvent(0, ev1, 0);
}